// round 4
// baseline (speedup 1.0000x reference)
#include <cuda_runtime.h>
#include <math.h>

// ---------------------------------------------------------------------------
// Problem constants: B=2, S=2048, DIM=2048, H=16, HDIM=128
// ---------------------------------------------------------------------------
#define DIMV 2048
#define GM   4096      // B*S rows
#define SEQ  2048
#define NHEAD 16
#define HDIM 128

// Scratch (device globals: allocation-free per harness rules)
__device__ float g_q  [GM * DIMV];
__device__ float g_k  [GM * DIMV];
__device__ float g_v  [GM * DIMV];
__device__ float g_qr [GM * DIMV];
__device__ float g_kr [GM * DIMV];
__device__ float g_att[GM * DIMV];
__device__ float g_tcos[SEQ * 64];
__device__ float g_tsin[SEQ * 64];

// ---------------------------------------------------------------------------
// Helpers
// ---------------------------------------------------------------------------
__device__ __forceinline__ float tf32r(float x) {
    unsigned u;
    asm("cvt.rna.tf32.f32 %0, %1;" : "=r"(u) : "f"(x));
    return __uint_as_float(u);
}

// mma.sync m16n8k8 tf32 fp32-accum (row.col).
// Frag layout (g=lane>>2, c=lane&3):
//   A: a0=(g,c) a1=(g+8,c) a2=(g,c+4) a3=(g+8,c+4)       [A is m x k]
//   B: b0=(k=c,n=g) b1=(k=c+4,n=g)                        [B is k x n]
//   C: c0=(g,2c) c1=(g,2c+1) c2=(g+8,2c) c3=(g+8,2c+1)
__device__ __forceinline__ void mma8(float* d, const float* a, const float* b) {
    asm volatile(
        "mma.sync.aligned.m16n8k8.row.col.f32.tf32.tf32.f32 "
        "{%0,%1,%2,%3}, {%4,%5,%6,%7}, {%8,%9}, {%0,%1,%2,%3};\n"
        : "+f"(d[0]), "+f"(d[1]), "+f"(d[2]), "+f"(d[3])
        : "r"(__float_as_uint(a[0])), "r"(__float_as_uint(a[1])),
          "r"(__float_as_uint(a[2])), "r"(__float_as_uint(a[3])),
          "r"(__float_as_uint(b[0])), "r"(__float_as_uint(b[1])));
}

// ---------------------------------------------------------------------------
// GEMM (NT): C[4096,2048] = A[4096,2048] * W[2048,2048]^T  (all row-major f32)
// 128x128x32 block tile, 256 threads (2x4 warps), warp tile 64x32.
// Smem stride 36 (== 4 mod 32): frag loads hit banks (4g+c) -> conflict-free.
// ---------------------------------------------------------------------------
__global__ __launch_bounds__(256, 2) void gemm_nt(const float* __restrict__ A,
                                                  const float* __restrict__ B,
                                                  float* __restrict__ C) {
    __shared__ float As[128][36];
    __shared__ float Bs[128][36];

    const int tid  = threadIdx.x;
    const int lane = tid & 31;
    const int wid  = tid >> 5;
    const int g    = lane >> 2;
    const int c    = lane & 3;
    const int wm   = wid & 1;   // m-warp (x64)
    const int wn   = wid >> 1;  // n-warp (x32)
    const int mbase = blockIdx.y * 128;
    const int nbase = blockIdx.x * 128;

    const int lr = tid >> 3;         // 0..31
    const int lc = (tid & 7) << 2;   // 0..28 step 4

    const float* Ap = A + (size_t)(mbase + lr) * DIMV + lc;
    const float* Bp = B + (size_t)(nbase + lr) * DIMV + lc;

    float acc[4][4][4];
#pragma unroll
    for (int i = 0; i < 4; i++)
#pragma unroll
        for (int j = 0; j < 4; j++)
#pragma unroll
            for (int e = 0; e < 4; e++) acc[i][j][e] = 0.f;

    float4 pa[4], pb[4];
#pragma unroll
    for (int r = 0; r < 4; r++) {
        pa[r] = *(const float4*)(Ap + (size_t)r * 32 * DIMV);
        pb[r] = *(const float4*)(Bp + (size_t)r * 32 * DIMV);
    }

    const int NT = DIMV / 32;
    for (int t = 0; t < NT; t++) {
        __syncthreads();
#pragma unroll
        for (int r = 0; r < 4; r++) {
            As[lr + 32 * r][lc + 0] = tf32r(pa[r].x);
            As[lr + 32 * r][lc + 1] = tf32r(pa[r].y);
            As[lr + 32 * r][lc + 2] = tf32r(pa[r].z);
            As[lr + 32 * r][lc + 3] = tf32r(pa[r].w);
            Bs[lr + 32 * r][lc + 0] = tf32r(pb[r].x);
            Bs[lr + 32 * r][lc + 1] = tf32r(pb[r].y);
            Bs[lr + 32 * r][lc + 2] = tf32r(pb[r].z);
            Bs[lr + 32 * r][lc + 3] = tf32r(pb[r].w);
        }
        __syncthreads();

        if (t + 1 < NT) {
            Ap += 32; Bp += 32;
#pragma unroll
            for (int r = 0; r < 4; r++) {
                pa[r] = *(const float4*)(Ap + (size_t)r * 32 * DIMV);
                pb[r] = *(const float4*)(Bp + (size_t)r * 32 * DIMV);
            }
        }

#pragma unroll
        for (int kk = 0; kk < 4; kk++) {
            const int k0 = kk << 3;
            float a[4][4];
#pragma unroll
            for (int mf = 0; mf < 4; mf++) {
                const int row = wm * 64 + mf * 16;
                a[mf][0] = As[row + g][k0 + c];
                a[mf][1] = As[row + g + 8][k0 + c];
                a[mf][2] = As[row + g][k0 + c + 4];
                a[mf][3] = As[row + g + 8][k0 + c + 4];
            }
#pragma unroll
            for (int nf = 0; nf < 4; nf++) {
                const int col = wn * 32 + nf * 8;
                float b2[2];
                b2[0] = Bs[col + g][k0 + c];
                b2[1] = Bs[col + g][k0 + c + 4];
#pragma unroll
                for (int mf = 0; mf < 4; mf++) mma8(acc[mf][nf], a[mf], b2);
            }
        }
    }

    // Epilogue: float2 stores (cols 2c,2c+1 contiguous)
#pragma unroll
    for (int mf = 0; mf < 4; mf++) {
        const int row = mbase + wm * 64 + mf * 16 + g;
#pragma unroll
        for (int nf = 0; nf < 4; nf++) {
            const int col = nbase + wn * 32 + nf * 8 + 2 * c;
            *(float2*)&C[(size_t)row * DIMV + col] =
                make_float2(acc[mf][nf][0], acc[mf][nf][1]);
            *(float2*)&C[(size_t)(row + 8) * DIMV + col] =
                make_float2(acc[mf][nf][2], acc[mf][nf][3]);
        }
    }
}

// ---------------------------------------------------------------------------
// RoPE tables: cos/sin(t * 10000^(-j/64)) in double precision, stored f32.
// ---------------------------------------------------------------------------
__global__ void rope_tables() {
    int idx = blockIdx.x * blockDim.x + threadIdx.x;
    if (idx >= SEQ * 64) return;
    int s = idx >> 6, j = idx & 63;
    double f = exp(-(double)j * (log(10000.0) / 64.0));
    double a = (double)s * f;
    g_tcos[idx] = (float)cos(a);
    g_tsin[idx] = (float)sin(a);
}

// ---------------------------------------------------------------------------
// RoPE apply (matches ref's interleaved-read / half-concat-write variant):
//   out[j]    = x[j]   *cos_j - x[2j+1]*sin_j
//   out[j+64] = x[j+64]*cos_j + x[2j]  *sin_j
// q additionally folded with the attention scale 1/sqrt(128).
// ---------------------------------------------------------------------------
__global__ void rope_apply() {
    int idx = blockIdx.x * blockDim.x + threadIdx.x;
    if (idx >= GM * NHEAD * 64) return;
    int j = idx & 63;
    int h = (idx >> 6) & (NHEAD - 1);
    int m = idx >> 10;
    int s = m & (SEQ - 1);
    size_t base = (size_t)m * DIMV + h * HDIM;
    float cs = g_tcos[(s << 6) + j];
    float sn = g_tsin[(s << 6) + j];
    const float SC = 0.08838834764831845f;  // 1/sqrt(128)
    {
        float xa = g_q[base + j], xb = g_q[base + j + 64];
        float x1 = g_q[base + 2 * j], x2 = g_q[base + 2 * j + 1];
        g_qr[base + j]      = (xa * cs - x2 * sn) * SC;
        g_qr[base + j + 64] = (xb * cs + x1 * sn) * SC;
    }
    {
        float xa = g_k[base + j], xb = g_k[base + j + 64];
        float x1 = g_k[base + 2 * j], x2 = g_k[base + 2 * j + 1];
        g_kr[base + j]      = xa * cs - x2 * sn;
        g_kr[base + j + 64] = xb * cs + x1 * sn;
    }
}

// ---------------------------------------------------------------------------
// Causal flash attention. One block = 64 query rows of one (b,h).
// 4 warps x 16 q-rows. Bkv=64. Online softmax, O accumulated via tf32 mma.
// Strides chosen mod 32 so all frag loads are bank-conflict-free:
//   Q/K stride 132 (->4g+c), V stride 136 (->8c+g), P stride 68 (->4g+c).
// ---------------------------------------------------------------------------
#define QSTR 132
#define KSTR 132
#define VSTR 136
#define PSTR 68
#define FLASH_SMEM ((64*QSTR + 64*KSTR + 64*VSTR + 4*16*PSTR) * 4)

__global__ __launch_bounds__(128, 1) void flash_kernel() {
    extern __shared__ float sm[];
    float* Qs = sm;                 // 64 x 132
    float* Ks = Qs + 64 * QSTR;     // 64 x 132
    float* Vs = Ks + 64 * KSTR;     // 64 x 136
    float* Ps = Vs + 64 * VSTR;     // 4 x (16 x 68)

    const int tid  = threadIdx.x;
    const int lane = tid & 31;
    const int w    = tid >> 5;
    const int g    = lane >> 2;
    const int c    = lane & 3;

    const int qt = (int)gridDim.x - 1 - (int)blockIdx.x;  // heavy tiles first
    const int h  = blockIdx.y;
    const int b  = blockIdx.z;
    const int q0 = qt * 64;
    const size_t brow = (size_t)b * SEQ;
    const int hcol = h * HDIM;

    // Stage Q once (tf32-rounded; scale already folded in RoPE)
    for (int idx = tid; idx < 64 * 32; idx += 128) {
        int qi = idx >> 5, d4 = (idx & 31) * 4;
        float4 v = *(const float4*)&g_qr[(brow + q0 + qi) * DIMV + hcol + d4];
        Qs[qi * QSTR + d4 + 0] = tf32r(v.x);
        Qs[qi * QSTR + d4 + 1] = tf32r(v.y);
        Qs[qi * QSTR + d4 + 2] = tf32r(v.z);
        Qs[qi * QSTR + d4 + 3] = tf32r(v.w);
    }

    float O[16][4];
#pragma unroll
    for (int nf = 0; nf < 16; nf++)
#pragma unroll
        for (int e = 0; e < 4; e++) O[nf][e] = 0.f;
    float m0 = -1e30f, m1 = -1e30f, l0 = 0.f, l1 = 0.f;
    float* Pw = Ps + w * 16 * PSTR;

    for (int kt = 0; kt <= qt; kt++) {
        __syncthreads();
        // Stage K and V tiles (row-major, tf32-rounded)
        for (int idx = tid; idx < 64 * 32; idx += 128) {
            int r = idx >> 5, d4 = (idx & 31) * 4;
            size_t go = (brow + (size_t)kt * 64 + r) * DIMV + hcol + d4;
            float4 kv = *(const float4*)&g_kr[go];
            Ks[r * KSTR + d4 + 0] = tf32r(kv.x);
            Ks[r * KSTR + d4 + 1] = tf32r(kv.y);
            Ks[r * KSTR + d4 + 2] = tf32r(kv.z);
            Ks[r * KSTR + d4 + 3] = tf32r(kv.w);
            float4 vv = *(const float4*)&g_v[go];
            Vs[r * VSTR + d4 + 0] = tf32r(vv.x);
            Vs[r * VSTR + d4 + 1] = tf32r(vv.y);
            Vs[r * VSTR + d4 + 2] = tf32r(vv.z);
            Vs[r * VSTR + d4 + 3] = tf32r(vv.w);
        }
        __syncthreads();

        // ---- S = Q K^T (16 x 64 per warp) ----
        float sacc[8][4];
#pragma unroll
        for (int nf = 0; nf < 8; nf++)
#pragma unroll
            for (int e = 0; e < 4; e++) sacc[nf][e] = 0.f;

        const int arow = (w * 16 + g) * QSTR;
#pragma unroll
        for (int k0 = 0; k0 < 128; k0 += 8) {
            float a[4];
            a[0] = Qs[arow + k0 + c];
            a[1] = Qs[arow + 8 * QSTR + k0 + c];
            a[2] = Qs[arow + k0 + c + 4];
            a[3] = Qs[arow + 8 * QSTR + k0 + c + 4];
#pragma unroll
            for (int nf = 0; nf < 8; nf++) {
                float b2[2];
                b2[0] = Ks[(nf * 8 + g) * KSTR + k0 + c];
                b2[1] = Ks[(nf * 8 + g) * KSTR + k0 + c + 4];
                mma8(sacc[nf], a, b2);
            }
        }

        // Causal mask on the diagonal tile
        if (kt == qt) {
            const int r0 = w * 16 + g;
#pragma unroll
            for (int nf = 0; nf < 8; nf++) {
                const int col0 = nf * 8 + 2 * c;
                if (col0     > r0)     sacc[nf][0] = -1e30f;
                if (col0 + 1 > r0)     sacc[nf][1] = -1e30f;
                if (col0     > r0 + 8) sacc[nf][2] = -1e30f;
                if (col0 + 1 > r0 + 8) sacc[nf][3] = -1e30f;
            }
        }

        // Row max across 16 cols in-thread + quad shuffle
        float rm0 = -1e30f, rm1 = -1e30f;
#pragma unroll
        for (int nf = 0; nf < 8; nf++) {
            rm0 = fmaxf(rm0, fmaxf(sacc[nf][0], sacc[nf][1]));
            rm1 = fmaxf(rm1, fmaxf(sacc[nf][2], sacc[nf][3]));
        }
        rm0 = fmaxf(rm0, __shfl_xor_sync(0xffffffffu, rm0, 1));
        rm0 = fmaxf(rm0, __shfl_xor_sync(0xffffffffu, rm0, 2));
        rm1 = fmaxf(rm1, __shfl_xor_sync(0xffffffffu, rm1, 1));
        rm1 = fmaxf(rm1, __shfl_xor_sync(0xffffffffu, rm1, 2));

        const float mn0 = fmaxf(m0, rm0), mn1 = fmaxf(m1, rm1);
        const float al0 = expf(m0 - mn0), al1 = expf(m1 - mn1);

        float p[8][4];
        float ps0 = 0.f, ps1 = 0.f;
#pragma unroll
        for (int nf = 0; nf < 8; nf++) {
            p[nf][0] = expf(sacc[nf][0] - mn0);
            p[nf][1] = expf(sacc[nf][1] - mn0);
            p[nf][2] = expf(sacc[nf][2] - mn1);
            p[nf][3] = expf(sacc[nf][3] - mn1);
            ps0 += p[nf][0] + p[nf][1];
            ps1 += p[nf][2] + p[nf][3];
        }
        ps0 += __shfl_xor_sync(0xffffffffu, ps0, 1);
        ps0 += __shfl_xor_sync(0xffffffffu, ps0, 2);
        ps1 += __shfl_xor_sync(0xffffffffu, ps1, 1);
        ps1 += __shfl_xor_sync(0xffffffffu, ps1, 2);
        l0 = l0 * al0 + ps0;
        l1 = l1 * al1 + ps1;
        m0 = mn0; m1 = mn1;

#pragma unroll
        for (int nf = 0; nf < 16; nf++) {
            O[nf][0] *= al0; O[nf][1] *= al0;
            O[nf][2] *= al1; O[nf][3] *= al1;
        }

        // P: C-layout -> smem -> A-layout (per-warp region)
#pragma unroll
        for (int nf = 0; nf < 8; nf++) {
            const int col = nf * 8 + 2 * c;
            *(float2*)&Pw[g * PSTR + col] =
                make_float2(tf32r(p[nf][0]), tf32r(p[nf][1]));
            *(float2*)&Pw[(g + 8) * PSTR + col] =
                make_float2(tf32r(p[nf][2]), tf32r(p[nf][3]));
        }
        __syncwarp();

        // ---- O += P V ----
#pragma unroll
        for (int k0 = 0; k0 < 64; k0 += 8) {
            float a[4];
            a[0] = Pw[g * PSTR + k0 + c];
            a[1] = Pw[(g + 8) * PSTR + k0 + c];
            a[2] = Pw[g * PSTR + k0 + c + 4];
            a[3] = Pw[(g + 8) * PSTR + k0 + c + 4];
#pragma unroll
            for (int nf = 0; nf < 16; nf++) {
                float b2[2];
                b2[0] = Vs[(k0 + c) * VSTR + nf * 8 + g];
                b2[1] = Vs[(k0 + c + 4) * VSTR + nf * 8 + g];
                mma8(O[nf], a, b2);
            }
        }
        __syncwarp();
    }

    // Epilogue: normalize and write [B,S,H*D] layout
    const float r0 = 1.f / l0, r1 = 1.f / l1;
    const int qrow = q0 + w * 16 + g;
#pragma unroll
    for (int nf = 0; nf < 16; nf++) {
        const int col = hcol + nf * 8 + 2 * c;
        *(float2*)&g_att[(brow + qrow) * DIMV + col] =
            make_float2(O[nf][0] * r0, O[nf][1] * r0);
        *(float2*)&g_att[(brow + qrow + 8) * DIMV + col] =
            make_float2(O[nf][2] * r1, O[nf][3] * r1);
    }
}

// ---------------------------------------------------------------------------
// Launch
// ---------------------------------------------------------------------------
extern "C" void kernel_launch(void* const* d_in, const int* in_sizes, int n_in,
                              void* d_out, int out_size) {
    (void)in_sizes; (void)n_in; (void)out_size;
    const float* x  = (const float*)d_in[0];
    const float* Wq = (const float*)d_in[1];
    const float* Wk = (const float*)d_in[2];
    const float* Wv = (const float*)d_in[3];
    const float* Wo = (const float*)d_in[4];
    float* out = (float*)d_out;

    float *pq, *pk, *pv, *patt;
    cudaGetSymbolAddress((void**)&pq,   g_q);
    cudaGetSymbolAddress((void**)&pk,   g_k);
    cudaGetSymbolAddress((void**)&pv,   g_v);
    cudaGetSymbolAddress((void**)&patt, g_att);

    cudaFuncSetAttribute(flash_kernel,
                         cudaFuncAttributeMaxDynamicSharedMemorySize,
                         FLASH_SMEM);

    dim3 gg(DIMV / 128, GM / 128);  // (16, 32)

    rope_tables<<<(SEQ * 64 + 255) / 256, 256>>>();
    gemm_nt<<<gg, 256>>>(x, Wq, pq);
    gemm_nt<<<gg, 256>>>(x, Wk, pk);
    gemm_nt<<<gg, 256>>>(x, Wv, pv);
    rope_apply<<<(GM * NHEAD * 64 + 255) / 256, 256>>>();
    flash_kernel<<<dim3(SEQ / 64, NHEAD, 2), 128, FLASH_SMEM>>>();
    gemm_nt<<<gg, 256>>>(patt, Wo, out);
}

// round 5
// speedup vs baseline: 1.1269x; 1.1269x over previous
#include <cuda_runtime.h>
#include <math.h>

// ---------------------------------------------------------------------------
// Problem constants: B=2, S=2048, DIM=2048, H=16, HDIM=128
// ---------------------------------------------------------------------------
#define DIMV 2048
#define GM   4096      // B*S rows
#define SEQ  2048
#define NHEAD 16
#define HDIM 128

// Scratch (device globals: allocation-free per harness rules)
__device__ float g_q  [GM * DIMV];
__device__ float g_k  [GM * DIMV];
__device__ float g_v  [GM * DIMV];
__device__ float g_qr [GM * DIMV];
__device__ float g_kr [GM * DIMV];
__device__ float g_att[GM * DIMV];
__device__ float g_xr [GM * DIMV];          // tf32-rounded x
__device__ float g_wqr[DIMV * DIMV];        // tf32-rounded weights
__device__ float g_wkr[DIMV * DIMV];
__device__ float g_wvr[DIMV * DIMV];
__device__ float g_wor[DIMV * DIMV];
__device__ float g_tcos[SEQ * 64];
__device__ float g_tsin[SEQ * 64];
__device__ float g_invf[64];

// ---------------------------------------------------------------------------
// Helpers
// ---------------------------------------------------------------------------
__device__ __forceinline__ float tf32r(float x) {
    unsigned u;
    asm("cvt.rna.tf32.f32 %0, %1;" : "=r"(u) : "f"(x));
    return __uint_as_float(u);
}

__device__ __forceinline__ unsigned smem_u32(const void* p) {
    return (unsigned)__cvta_generic_to_shared(p);
}

#define CP_ASYNC16(dst_u32, src) \
    asm volatile("cp.async.cg.shared.global [%0], [%1], 16;\n" :: "r"(dst_u32), "l"(src))
#define CP_COMMIT() asm volatile("cp.async.commit_group;\n" ::)
#define CP_WAIT1()  asm volatile("cp.async.wait_group 1;\n" ::)
#define CP_WAIT0()  asm volatile("cp.async.wait_group 0;\n" ::)

// mma.sync m16n8k8 tf32 fp32-accum (row.col).
// Frag layout (g=lane>>2, c=lane&3):
//   A: a0=(g,c) a1=(g+8,c) a2=(g,c+4) a3=(g+8,c+4)       [A is m x k]
//   B: b0=(k=c,n=g) b1=(k=c+4,n=g)                        [B is k x n]
//   C: c0=(g,2c) c1=(g,2c+1) c2=(g+8,2c) c3=(g+8,2c+1)
__device__ __forceinline__ void mma8(float* d, const float* a, const float* b) {
    asm volatile(
        "mma.sync.aligned.m16n8k8.row.col.f32.tf32.tf32.f32 "
        "{%0,%1,%2,%3}, {%4,%5,%6,%7}, {%8,%9}, {%0,%1,%2,%3};\n"
        : "+f"(d[0]), "+f"(d[1]), "+f"(d[2]), "+f"(d[3])
        : "r"(__float_as_uint(a[0])), "r"(__float_as_uint(a[1])),
          "r"(__float_as_uint(a[2])), "r"(__float_as_uint(a[3])),
          "r"(__float_as_uint(b[0])), "r"(__float_as_uint(b[1])));
}

// ---------------------------------------------------------------------------
// tf32 pre-round pass (float4 vectorized)
// ---------------------------------------------------------------------------
__global__ void round_copy(const float* __restrict__ src, float* __restrict__ dst,
                           int n4) {
    int i = blockIdx.x * blockDim.x + threadIdx.x;
    if (i >= n4) return;
    float4 v = ((const float4*)src)[i];
    v.x = tf32r(v.x); v.y = tf32r(v.y); v.z = tf32r(v.z); v.w = tf32r(v.w);
    ((float4*)dst)[i] = v;
}

// ---------------------------------------------------------------------------
// GEMM (NT): C[4096,2048] = A[4096,2048] * W[2048,2048]^T, inputs pre-rounded.
// 128x128x32 block tile, 256 threads (2x4 warps), warp tile 64x32.
// cp.async 2-stage pipeline. Smem stride 36 (==4 mod 32): frag loads hit
// banks (4g+c) -> conflict-free. Stage = A[128][36] + B[128][36].
// ---------------------------------------------------------------------------
#define GSTR 36
#define GEMM_STAGE (128 * GSTR)           // floats per matrix per stage
#define GEMM_SMEM  (4 * GEMM_STAGE * 4)   // 2 stages x (A+B) bytes = 73728

__global__ __launch_bounds__(256, 2) void gemm_nt(const float* __restrict__ A,
                                                  const float* __restrict__ B,
                                                  float* __restrict__ C) {
    extern __shared__ float sm[];
    // layout: [stage][A(4608) | B(4608)]
    const int tid  = threadIdx.x;
    const int lane = tid & 31;
    const int wid  = tid >> 5;
    const int g    = lane >> 2;
    const int c    = lane & 3;
    const int wm   = wid & 1;
    const int wn   = wid >> 1;
    const int mbase = blockIdx.y * 128;
    const int nbase = blockIdx.x * 128;

    const int lr = tid >> 3;         // 0..31
    const int lc = (tid & 7) << 2;   // 0..28 step 4

    const float* Ap = A + (size_t)(mbase + lr) * DIMV + lc;
    const float* Bp = B + (size_t)(nbase + lr) * DIMV + lc;

    // per-thread smem destinations (stage 0), 4 rows each for A and B
    unsigned sA = smem_u32(&sm[lr * GSTR + lc]);
    unsigned sB = smem_u32(&sm[GEMM_STAGE + lr * GSTR + lc]);
    const unsigned stageB = 2 * GEMM_STAGE * 4;  // bytes per stage

    float acc[4][4][4];
#pragma unroll
    for (int i = 0; i < 4; i++)
#pragma unroll
        for (int j = 0; j < 4; j++)
#pragma unroll
            for (int e = 0; e < 4; e++) acc[i][j][e] = 0.f;

    // prologue: stage 0
#pragma unroll
    for (int r = 0; r < 4; r++) {
        CP_ASYNC16(sA + r * 32 * GSTR * 4, Ap + (size_t)r * 32 * DIMV);
        CP_ASYNC16(sB + r * 32 * GSTR * 4, Bp + (size_t)r * 32 * DIMV);
    }
    CP_COMMIT();

    const int NT = DIMV / 32;
    for (int t = 0; t < NT; t++) {
        if (t + 1 < NT) {
            const float* An = Ap + (t + 1) * 32;
            const float* Bn = Bp + (t + 1) * 32;
            const unsigned so = ((t + 1) & 1) * stageB;
#pragma unroll
            for (int r = 0; r < 4; r++) {
                CP_ASYNC16(sA + so + r * 32 * GSTR * 4, An + (size_t)r * 32 * DIMV);
                CP_ASYNC16(sB + so + r * 32 * GSTR * 4, Bn + (size_t)r * 32 * DIMV);
            }
            CP_COMMIT();
            CP_WAIT1();
        } else {
            CP_WAIT0();
        }
        __syncthreads();

        const float* As = sm + (t & 1) * 2 * GEMM_STAGE;
        const float* Bs = As + GEMM_STAGE;

#pragma unroll
        for (int kk = 0; kk < 4; kk++) {
            const int k0 = kk << 3;
            float a[4][4];
#pragma unroll
            for (int mf = 0; mf < 4; mf++) {
                const int row = wm * 64 + mf * 16;
                a[mf][0] = As[(row + g) * GSTR + k0 + c];
                a[mf][1] = As[(row + g + 8) * GSTR + k0 + c];
                a[mf][2] = As[(row + g) * GSTR + k0 + c + 4];
                a[mf][3] = As[(row + g + 8) * GSTR + k0 + c + 4];
            }
#pragma unroll
            for (int nf = 0; nf < 4; nf++) {
                const int col = wn * 32 + nf * 8;
                float b2[2];
                b2[0] = Bs[(col + g) * GSTR + k0 + c];
                b2[1] = Bs[(col + g) * GSTR + k0 + c + 4];
#pragma unroll
                for (int mf = 0; mf < 4; mf++) mma8(acc[mf][nf], a[mf], b2);
            }
        }
        __syncthreads();
    }

    // Epilogue: float2 stores (cols 2c,2c+1 contiguous)
#pragma unroll
    for (int mf = 0; mf < 4; mf++) {
        const int row = mbase + wm * 64 + mf * 16 + g;
#pragma unroll
        for (int nf = 0; nf < 4; nf++) {
            const int col = nbase + wn * 32 + nf * 8 + 2 * c;
            *(float2*)&C[(size_t)row * DIMV + col] =
                make_float2(acc[mf][nf][0], acc[mf][nf][1]);
            *(float2*)&C[(size_t)(row + 8) * DIMV + col] =
                make_float2(acc[mf][nf][2], acc[mf][nf][3]);
        }
    }
}

// ---------------------------------------------------------------------------
// RoPE tables. Only 64 distinct inv_freq values -> tiny FP64 kernel, then
// float-only table build (also matches the reference's float32 pipeline).
// ---------------------------------------------------------------------------
__global__ void invf_kernel() {
    int j = threadIdx.x;
    if (j < 64)
        g_invf[j] = (float)exp(-(double)j * 0.14391156831212787);  // ln(1e4)/64
}

__global__ void rope_tables() {
    int idx = blockIdx.x * blockDim.x + threadIdx.x;
    if (idx >= SEQ * 64) return;
    int s = idx >> 6, j = idx & 63;
    float a = (float)s * g_invf[j];
    float sn, cs;
    sincosf(a, &sn, &cs);
    g_tcos[idx] = cs;
    g_tsin[idx] = sn;
}

// ---------------------------------------------------------------------------
// RoPE apply (matches ref's interleaved-read / half-concat-write variant):
//   out[j]    = x[j]   *cos_j - x[2j+1]*sin_j
//   out[j+64] = x[j+64]*cos_j + x[2j]  *sin_j
// q additionally folded with the attention scale 1/sqrt(128).
// ---------------------------------------------------------------------------
__global__ void rope_apply() {
    int idx = blockIdx.x * blockDim.x + threadIdx.x;
    if (idx >= GM * NHEAD * 64) return;
    int j = idx & 63;
    int h = (idx >> 6) & (NHEAD - 1);
    int m = idx >> 10;
    int s = m & (SEQ - 1);
    size_t base = (size_t)m * DIMV + h * HDIM;
    float cs = g_tcos[(s << 6) + j];
    float sn = g_tsin[(s << 6) + j];
    const float SC = 0.08838834764831845f;  // 1/sqrt(128)
    {
        float xa = g_q[base + j], xb = g_q[base + j + 64];
        float x1 = g_q[base + 2 * j], x2 = g_q[base + 2 * j + 1];
        g_qr[base + j]      = (xa * cs - x2 * sn) * SC;
        g_qr[base + j + 64] = (xb * cs + x1 * sn) * SC;
    }
    {
        float xa = g_k[base + j], xb = g_k[base + j + 64];
        float x1 = g_k[base + 2 * j], x2 = g_k[base + 2 * j + 1];
        g_kr[base + j]      = xa * cs - x2 * sn;
        g_kr[base + j + 64] = xb * cs + x1 * sn;
    }
}

// ---------------------------------------------------------------------------
// Causal flash attention. One block = 64 query rows of one (b,h).
// 4 warps x 16 q-rows. Bkv=64. Online softmax, O via tf32 mma.
// P buffer ALIASES the K region (K is dead once S is computed; a barrier
// separates the last K read from the first P write), cutting smem to
// 102.4KB -> 2 CTAs/SM.
// Strides mod 32 keep all frag loads bank-conflict-free:
//   Q/K stride 132 (->4g+c), V stride 136 (->8c+g), P stride 68 (->4g+c).
// ---------------------------------------------------------------------------
#define QSTR 132
#define KSTR 132
#define VSTR 136
#define PSTR 68
#define FLASH_SMEM ((64 * QSTR + 64 * KSTR + 64 * VSTR) * 4)   // 102400 B

__global__ __launch_bounds__(128) void flash_kernel() {
    extern __shared__ float sm[];
    float* Qs = sm;                 // 64 x 132
    float* Ks = Qs + 64 * QSTR;     // 64 x 132  (re-used as P after S phase)
    float* Vs = Ks + 64 * KSTR;     // 64 x 136

    const int tid  = threadIdx.x;
    const int lane = tid & 31;
    const int w    = tid >> 5;
    const int g    = lane >> 2;
    const int c    = lane & 3;

    const int qt = (int)gridDim.x - 1 - (int)blockIdx.x;  // heavy tiles first
    const int h  = blockIdx.y;
    const int b  = blockIdx.z;
    const int q0 = qt * 64;
    const size_t brow = (size_t)b * SEQ;
    const int hcol = h * HDIM;

    // Stage Q once (tf32-rounded; scale already folded in RoPE)
    for (int idx = tid; idx < 64 * 32; idx += 128) {
        int qi = idx >> 5, d4 = (idx & 31) * 4;
        float4 v = *(const float4*)&g_qr[(brow + q0 + qi) * DIMV + hcol + d4];
        Qs[qi * QSTR + d4 + 0] = tf32r(v.x);
        Qs[qi * QSTR + d4 + 1] = tf32r(v.y);
        Qs[qi * QSTR + d4 + 2] = tf32r(v.z);
        Qs[qi * QSTR + d4 + 3] = tf32r(v.w);
    }

    float O[16][4];
#pragma unroll
    for (int nf = 0; nf < 16; nf++)
#pragma unroll
        for (int e = 0; e < 4; e++) O[nf][e] = 0.f;
    float m0 = -1e30f, m1 = -1e30f, l0 = 0.f, l1 = 0.f;
    float* Pw = Ks + w * 16 * PSTR;   // alias into K region

    for (int kt = 0; kt <= qt; kt++) {
        __syncthreads();   // prior tile's P reads + this-tile restaging order
        // Stage K and V tiles (row-major, tf32-rounded)
        for (int idx = tid; idx < 64 * 32; idx += 128) {
            int r = idx >> 5, d4 = (idx & 31) * 4;
            size_t go = (brow + (size_t)kt * 64 + r) * DIMV + hcol + d4;
            float4 kv = *(const float4*)&g_kr[go];
            Ks[r * KSTR + d4 + 0] = tf32r(kv.x);
            Ks[r * KSTR + d4 + 1] = tf32r(kv.y);
            Ks[r * KSTR + d4 + 2] = tf32r(kv.z);
            Ks[r * KSTR + d4 + 3] = tf32r(kv.w);
            float4 vv = *(const float4*)&g_v[go];
            Vs[r * VSTR + d4 + 0] = tf32r(vv.x);
            Vs[r * VSTR + d4 + 1] = tf32r(vv.y);
            Vs[r * VSTR + d4 + 2] = tf32r(vv.z);
            Vs[r * VSTR + d4 + 3] = tf32r(vv.w);
        }
        __syncthreads();

        // ---- S = Q K^T (16 x 64 per warp) ----
        float sacc[8][4];
#pragma unroll
        for (int nf = 0; nf < 8; nf++)
#pragma unroll
            for (int e = 0; e < 4; e++) sacc[nf][e] = 0.f;

        const int arow = (w * 16 + g) * QSTR;
#pragma unroll
        for (int k0 = 0; k0 < 128; k0 += 8) {
            float a[4];
            a[0] = Qs[arow + k0 + c];
            a[1] = Qs[arow + 8 * QSTR + k0 + c];
            a[2] = Qs[arow + k0 + c + 4];
            a[3] = Qs[arow + 8 * QSTR + k0 + c + 4];
#pragma unroll
            for (int nf = 0; nf < 8; nf++) {
                float b2[2];
                b2[0] = Ks[(nf * 8 + g) * KSTR + k0 + c];
                b2[1] = Ks[(nf * 8 + g) * KSTR + k0 + c + 4];
                mma8(sacc[nf], a, b2);
            }
        }

        // Causal mask on the diagonal tile
        if (kt == qt) {
            const int r0 = w * 16 + g;
#pragma unroll
            for (int nf = 0; nf < 8; nf++) {
                const int col0 = nf * 8 + 2 * c;
                if (col0     > r0)     sacc[nf][0] = -1e30f;
                if (col0 + 1 > r0)     sacc[nf][1] = -1e30f;
                if (col0     > r0 + 8) sacc[nf][2] = -1e30f;
                if (col0 + 1 > r0 + 8) sacc[nf][3] = -1e30f;
            }
        }

        // Row max across 16 cols in-thread + quad shuffle
        float rm0 = -1e30f, rm1 = -1e30f;
#pragma unroll
        for (int nf = 0; nf < 8; nf++) {
            rm0 = fmaxf(rm0, fmaxf(sacc[nf][0], sacc[nf][1]));
            rm1 = fmaxf(rm1, fmaxf(sacc[nf][2], sacc[nf][3]));
        }
        rm0 = fmaxf(rm0, __shfl_xor_sync(0xffffffffu, rm0, 1));
        rm0 = fmaxf(rm0, __shfl_xor_sync(0xffffffffu, rm0, 2));
        rm1 = fmaxf(rm1, __shfl_xor_sync(0xffffffffu, rm1, 1));
        rm1 = fmaxf(rm1, __shfl_xor_sync(0xffffffffu, rm1, 2));

        const float mn0 = fmaxf(m0, rm0), mn1 = fmaxf(m1, rm1);
        const float al0 = expf(m0 - mn0), al1 = expf(m1 - mn1);

        float p[8][4];
        float ps0 = 0.f, ps1 = 0.f;
#pragma unroll
        for (int nf = 0; nf < 8; nf++) {
            p[nf][0] = expf(sacc[nf][0] - mn0);
            p[nf][1] = expf(sacc[nf][1] - mn0);
            p[nf][2] = expf(sacc[nf][2] - mn1);
            p[nf][3] = expf(sacc[nf][3] - mn1);
            ps0 += p[nf][0] + p[nf][1];
            ps1 += p[nf][2] + p[nf][3];
        }
        ps0 += __shfl_xor_sync(0xffffffffu, ps0, 1);
        ps0 += __shfl_xor_sync(0xffffffffu, ps0, 2);
        ps1 += __shfl_xor_sync(0xffffffffu, ps1, 1);
        ps1 += __shfl_xor_sync(0xffffffffu, ps1, 2);
        l0 = l0 * al0 + ps0;
        l1 = l1 * al1 + ps1;
        m0 = mn0; m1 = mn1;

#pragma unroll
        for (int nf = 0; nf < 16; nf++) {
            O[nf][0] *= al0; O[nf][1] *= al0;
            O[nf][2] *= al1; O[nf][3] *= al1;
        }

        // All warps must be done READING K before P overwrites its region
        __syncthreads();

        // P: C-layout -> smem (K region) -> A-layout (per-warp slice)
#pragma unroll
        for (int nf = 0; nf < 8; nf++) {
            const int col = nf * 8 + 2 * c;
            *(float2*)&Pw[g * PSTR + col] =
                make_float2(tf32r(p[nf][0]), tf32r(p[nf][1]));
            *(float2*)&Pw[(g + 8) * PSTR + col] =
                make_float2(tf32r(p[nf][2]), tf32r(p[nf][3]));
        }
        __syncwarp();

        // ---- O += P V ----
#pragma unroll
        for (int k0 = 0; k0 < 64; k0 += 8) {
            float a[4];
            a[0] = Pw[g * PSTR + k0 + c];
            a[1] = Pw[(g + 8) * PSTR + k0 + c];
            a[2] = Pw[g * PSTR + k0 + c + 4];
            a[3] = Pw[(g + 8) * PSTR + k0 + c + 4];
#pragma unroll
            for (int nf = 0; nf < 16; nf++) {
                float b2[2];
                b2[0] = Vs[(k0 + c) * VSTR + nf * 8 + g];
                b2[1] = Vs[(k0 + c + 4) * VSTR + nf * 8 + g];
                mma8(O[nf], a, b2);
            }
        }
        __syncwarp();
    }

    // Epilogue: normalize, tf32-round (feeds the pre-rounded Wo GEMM),
    // write [B,S,H*D]
    const float r0 = 1.f / l0, r1 = 1.f / l1;
    const int qrow = q0 + w * 16 + g;
#pragma unroll
    for (int nf = 0; nf < 16; nf++) {
        const int col = hcol + nf * 8 + 2 * c;
        *(float2*)&g_att[(brow + qrow) * DIMV + col] =
            make_float2(tf32r(O[nf][0] * r0), tf32r(O[nf][1] * r0));
        *(float2*)&g_att[(brow + qrow + 8) * DIMV + col] =
            make_float2(tf32r(O[nf][2] * r1), tf32r(O[nf][3] * r1));
    }
}

// ---------------------------------------------------------------------------
// Launch
// ---------------------------------------------------------------------------
extern "C" void kernel_launch(void* const* d_in, const int* in_sizes, int n_in,
                              void* d_out, int out_size) {
    (void)in_sizes; (void)n_in; (void)out_size;
    const float* x  = (const float*)d_in[0];
    const float* Wq = (const float*)d_in[1];
    const float* Wk = (const float*)d_in[2];
    const float* Wv = (const float*)d_in[3];
    const float* Wo = (const float*)d_in[4];
    float* out = (float*)d_out;

    float *pq, *pk, *pv, *patt, *pxr, *pwq, *pwk, *pwv, *pwo;
    cudaGetSymbolAddress((void**)&pq,   g_q);
    cudaGetSymbolAddress((void**)&pk,   g_k);
    cudaGetSymbolAddress((void**)&pv,   g_v);
    cudaGetSymbolAddress((void**)&patt, g_att);
    cudaGetSymbolAddress((void**)&pxr,  g_xr);
    cudaGetSymbolAddress((void**)&pwq,  g_wqr);
    cudaGetSymbolAddress((void**)&pwk,  g_wkr);
    cudaGetSymbolAddress((void**)&pwv,  g_wvr);
    cudaGetSymbolAddress((void**)&pwo,  g_wor);

    cudaFuncSetAttribute(gemm_nt,
                         cudaFuncAttributeMaxDynamicSharedMemorySize, GEMM_SMEM);
    cudaFuncSetAttribute(flash_kernel,
                         cudaFuncAttributeMaxDynamicSharedMemorySize, FLASH_SMEM);

    const int NX4 = GM * DIMV / 4;     // x elements / 4
    const int NW4 = DIMV * DIMV / 4;   // weight elements / 4
    round_copy<<<(NX4 + 255) / 256, 256>>>(x,  pxr, NX4);
    round_copy<<<(NW4 + 255) / 256, 256>>>(Wq, pwq, NW4);
    round_copy<<<(NW4 + 255) / 256, 256>>>(Wk, pwk, NW4);
    round_copy<<<(NW4 + 255) / 256, 256>>>(Wv, pwv, NW4);
    round_copy<<<(NW4 + 255) / 256, 256>>>(Wo, pwo, NW4);

    invf_kernel<<<1, 64>>>();
    rope_tables<<<(SEQ * 64 + 255) / 256, 256>>>();

    dim3 gg(DIMV / 128, GM / 128);  // (16, 32)
    gemm_nt<<<gg, 256, GEMM_SMEM>>>(pxr, pwq, pq);
    gemm_nt<<<gg, 256, GEMM_SMEM>>>(pxr, pwk, pk);
    gemm_nt<<<gg, 256, GEMM_SMEM>>>(pxr, pwv, pv);
    rope_apply<<<(GM * NHEAD * 64 + 255) / 256, 256>>>();
    flash_kernel<<<dim3(SEQ / 64, NHEAD, 2), 128, FLASH_SMEM>>>();
    gemm_nt<<<gg, 256, GEMM_SMEM>>>(patt, pwo, out);
}